// round 15
// baseline (speedup 1.0000x reference)
#include <cuda_runtime.h>
#include <cstdint>

// GriddingReverse: grid [B,128,128,128] fp32 -> ptcloud [B, 128^3, 3] fp32.
//
// Round-15: single-variable change vs R14: __launch_bounds__(256, 8)
// (regs 40 -> 32 cap, 8 CTAs/SM). R14 profile is latency-bound (issue 55.9%,
// L1 63.9%, nothing saturated, occ 62%); more resident warps -> more loads
// in flight. All else unchanged:
//   - row-pair per warp, 6 LDG.128 (MLP=6), shfl z-neighbor
//   - s8 algebraic rewrite + folded epilogue (2 FMA/coordinate)
//   - smem staging + per-warp 3KB cp.async.bulk drain, evict_first policy

#define S 128
#define EPSF 1e-6f

__device__ __forceinline__ void zero_row(float4* s, int t)
{
    const float4 z4 = make_float4(0.f, 0.f, 0.f, 0.f);
    s[t * 3 + 0] = z4;
    s[t * 3 + 1] = z4;
    s[t * 3 + 2] = z4;
}

// Compute one output row from its 4 corner input rows.
// B00=(x-1,y-1) B01=(x-1,y) B10=(x,y-1) B11=(x,y); aXX = lane t-1's .w of BXX.
__device__ __forceinline__ void compute_row(
    float4 B00, float4 B01, float4 B10, float4 B11,
    float a00, float a01, float a10, float a11,
    float xf, float yf, float zf0, int t, float4* s)
{
    const float hi00[4] = {B00.x, B00.y, B00.z, B00.w};
    const float hi01[4] = {B01.x, B01.y, B01.z, B01.w};
    const float hi10[4] = {B10.x, B10.y, B10.z, B10.w};
    const float hi11[4] = {B11.x, B11.y, B11.z, B11.w};
    const float lo00[4] = {a00, B00.x, B00.y, B00.z};
    const float lo01[4] = {a01, B01.x, B01.y, B01.z};
    const float lo10[4] = {a10, B10.x, B10.y, B10.z};
    const float lo11[4] = {a11, B11.x, B11.y, B11.z};

    float res[12];

#pragma unroll
    for (int j = 0; j < 4; ++j) {
        const float p00 = lo00[j] + hi00[j];
        const float p01 = lo01[j] + hi01[j];
        const float p10 = lo10[j] + hi10[j];
        const float p11 = lo11[j] + hi11[j];

        const float x_lo = p00 + p01;                     // dx = 0 corners
        const float x_hi = p10 + p11;                     // dx = 1 corners
        const float s8   = x_lo + x_hi;                   // all 8 corners
        const float y_lo = p00 + p10;                     // dy = 0
        const float z_lo = (lo00[j] + lo01[j]) + (lo10[j] + lo11[j]);

        // (num/wsum - 64) * (1/64) == fma(num, (1/64)/wsum, -1)   [64*(1/64)==1]
        const float inv_s = __fdividef(0.015625f, s8 + EPSF);
        const float zf = zf0 + (float)j;

        // hi*c + lo*(c-1) == s8*c - lo
        float px = fmaf(fmaf(s8, xf, -x_lo), inv_s, -1.0f);
        float py = fmaf(fmaf(s8, yf, -y_lo), inv_s, -1.0f);
        float pz = fmaf(fmaf(s8, zf, -z_lo), inv_s, -1.0f);

        if (t == 0 && j == 0) { px = 0.f; py = 0.f; pz = 0.f; }  // z==0

        res[j * 3 + 0] = px;
        res[j * 3 + 1] = py;
        res[j * 3 + 2] = pz;
    }

    s[t * 3 + 0] = make_float4(res[0], res[1],  res[2],  res[3]);
    s[t * 3 + 1] = make_float4(res[4], res[5],  res[6],  res[7]);
    s[t * 3 + 2] = make_float4(res[8], res[9],  res[10], res[11]);
}

__global__ void __launch_bounds__(256, 8)
gridding_reverse_kernel(const float4* __restrict__ g4,
                        float4* __restrict__ out4)
{
    __shared__ __align__(16) float4 stage[1536];  // 16 rows * 96 float4 = 24KB

    const int tid = threadIdx.x;
    const int t   = tid & 31;                     // lane == z-group (4 points)
    const int wid = tid >> 5;
    const int w2  = blockIdx.x * 8 + wid;         // row-pair id

    const int y0 = (w2 & 63) << 1;                // even y of the pair
    const int x  = (w2 >> 6) & (S - 1);
    const int b  = w2 >> 13;

    float4* s = &stage[wid * 192];

    if (x == 0) {
        zero_row(s, t);
        zero_row(s + 96, t);
    } else {
        const int ym1 = (y0 == 0) ? 0 : (y0 - 1);   // clamped; row y0 zeroed anyway

        // row base (b, X, Y) in float4 units = ((b*S + X)*S + Y)*32
        const int gx0 = ((b * S + (x - 1)) * S) * 32 + t;   // X = x-1
        const int gx1 = gx0 + S * 32;                       // X = x

        const float4 A0 = __ldg(g4 + gx0 + ym1 * 32);       // (x-1, y-1)
        const float4 A1 = __ldg(g4 + gx0 + y0 * 32);        // (x-1, y  )
        const float4 A2 = __ldg(g4 + gx0 + (y0 + 1) * 32);  // (x-1, y+1)
        const float4 C0 = __ldg(g4 + gx1 + ym1 * 32);       // (x  , y-1)
        const float4 C1 = __ldg(g4 + gx1 + y0 * 32);        // (x  , y  )
        const float4 C2 = __ldg(g4 + gx1 + (y0 + 1) * 32);  // (x  , y+1)

        const float aA0 = __shfl_up_sync(0xffffffffu, A0.w, 1);
        const float aA1 = __shfl_up_sync(0xffffffffu, A1.w, 1);
        const float aA2 = __shfl_up_sync(0xffffffffu, A2.w, 1);
        const float aC0 = __shfl_up_sync(0xffffffffu, C0.w, 1);
        const float aC1 = __shfl_up_sync(0xffffffffu, C1.w, 1);
        const float aC2 = __shfl_up_sync(0xffffffffu, C2.w, 1);

        const float xf  = (float)x;
        const float zf0 = (float)(t * 4);

        if (y0 == 0) {
            zero_row(s, t);                          // y==0 boundary row
        } else {
            compute_row(A0, A1, C0, C1, aA0, aA1, aC0, aC1,
                        xf, (float)y0, zf0, t, s);
        }
        compute_row(A1, A2, C1, C2, aA1, aA2, aC1, aC2,
                    xf, (float)(y0 + 1), zf0, t, s + 96);
    }

    // per-warp drain: this warp's 3KB stage region -> contiguous 3KB of out,
    // tagged evict_first so dead output lines don't evict the live input.
    __syncwarp();
    if (t == 0) {
        float4* dst = out4 + (size_t)blockIdx.x * 1536 + wid * 192;
        unsigned int smem_addr;
        asm("{ .reg .u64 a; cvta.to.shared.u64 a, %1; cvt.u32.u64 %0, a; }"
            : "=r"(smem_addr) : "l"(s));
        unsigned long long pol;
        asm("createpolicy.fractional.L2::evict_first.b64 %0, 1.0;" : "=l"(pol));
        asm volatile("fence.proxy.async.shared::cta;" ::: "memory");
        asm volatile(
            "cp.async.bulk.global.shared::cta.bulk_group.L2::cache_hint "
            "[%0], [%1], %2, %3;"
            :: "l"(dst), "r"(smem_addr), "r"(3072), "l"(pol) : "memory");
        asm volatile("cp.async.bulk.commit_group;" ::: "memory");
        asm volatile("cp.async.bulk.wait_group 0;" ::: "memory");
    }
}

extern "C" void kernel_launch(void* const* d_in, const int* in_sizes, int n_in,
                              void* d_out, int out_size)
{
    const float4* g4 = (const float4*)d_in[0];
    float4* o4 = (float4*)d_out;

    const int total = in_sizes[0];          // B * 128^3
    const int nb = total >> 21;             // B
    const int npairs = nb * S * (S / 2);    // one warp per row pair
    const int blocks = npairs / 8;          // 8 pairs per 256-thread block

    gridding_reverse_kernel<<<blocks, 256>>>(g4, o4);
}

// round 16
// speedup vs baseline: 1.2905x; 1.2905x over previous
#include <cuda_runtime.h>
#include <cstdint>

// GriddingReverse: grid [B,128,128,128] fp32 -> ptcloud [B, 128^3, 3] fp32.
//
// Round-16: R15 (regs-32 cap) spilled and regressed (occ 85% but issue 41%).
// Occupancy is a dead lever; per-warp efficiency is what pays. Re-try the
// heavy-warp direction (R10's best-ever ncu 21.95us) now that evict_first
// fixed the L2-pollution that poisoned its bench score:
//   - one warp per 2x2 output-row tile (x0,x0+1) x (y0,y0+1): the 4 rows
//     share a 3x3 input-row neighborhood -> 9 LDG.128 / 4 rows (was 12),
//     9 shfl (was 12), per-warp overhead amortized 4x
//   - __launch_bounds__(256,4): 64-reg budget, no forced spills
//   - s8 algebraic rewrite + folded epilogue (2 FMA/coordinate)
//   - smem staging; per-warp drain = two 3KB cp.async.bulk (evict_first)

#define S 128
#define EPSF 1e-6f

__device__ __forceinline__ void zero_row(float4* s, int t)
{
    const float4 z4 = make_float4(0.f, 0.f, 0.f, 0.f);
    s[t * 3 + 0] = z4;
    s[t * 3 + 1] = z4;
    s[t * 3 + 2] = z4;
}

// Compute one output row from its 4 corner input rows.
// B00=(x-1,y-1) B01=(x-1,y) B10=(x,y-1) B11=(x,y); aXX = lane t-1's .w of BXX.
__device__ __forceinline__ void compute_row(
    float4 B00, float4 B01, float4 B10, float4 B11,
    float a00, float a01, float a10, float a11,
    float xf, float yf, float zf0, int t, float4* s)
{
    const float hi00[4] = {B00.x, B00.y, B00.z, B00.w};
    const float hi01[4] = {B01.x, B01.y, B01.z, B01.w};
    const float hi10[4] = {B10.x, B10.y, B10.z, B10.w};
    const float hi11[4] = {B11.x, B11.y, B11.z, B11.w};
    const float lo00[4] = {a00, B00.x, B00.y, B00.z};
    const float lo01[4] = {a01, B01.x, B01.y, B01.z};
    const float lo10[4] = {a10, B10.x, B10.y, B10.z};
    const float lo11[4] = {a11, B11.x, B11.y, B11.z};

    float res[12];

#pragma unroll
    for (int j = 0; j < 4; ++j) {
        const float p00 = lo00[j] + hi00[j];
        const float p01 = lo01[j] + hi01[j];
        const float p10 = lo10[j] + hi10[j];
        const float p11 = lo11[j] + hi11[j];

        const float x_lo = p00 + p01;                     // dx = 0 corners
        const float x_hi = p10 + p11;                     // dx = 1 corners
        const float s8   = x_lo + x_hi;                   // all 8 corners
        const float y_lo = p00 + p10;                     // dy = 0
        const float z_lo = (lo00[j] + lo01[j]) + (lo10[j] + lo11[j]);

        // (num/wsum - 64) * (1/64) == fma(num, (1/64)/wsum, -1)   [64*(1/64)==1]
        const float inv_s = __fdividef(0.015625f, s8 + EPSF);
        const float zf = zf0 + (float)j;

        // hi*c + lo*(c-1) == s8*c - lo
        float px = fmaf(fmaf(s8, xf, -x_lo), inv_s, -1.0f);
        float py = fmaf(fmaf(s8, yf, -y_lo), inv_s, -1.0f);
        float pz = fmaf(fmaf(s8, zf, -z_lo), inv_s, -1.0f);

        if (t == 0 && j == 0) { px = 0.f; py = 0.f; pz = 0.f; }  // z==0

        res[j * 3 + 0] = px;
        res[j * 3 + 1] = py;
        res[j * 3 + 2] = pz;
    }

    s[t * 3 + 0] = make_float4(res[0], res[1],  res[2],  res[3]);
    s[t * 3 + 1] = make_float4(res[4], res[5],  res[6],  res[7]);
    s[t * 3 + 2] = make_float4(res[8], res[9],  res[10], res[11]);
}

__global__ void __launch_bounds__(256, 4)
gridding_reverse_kernel(const float4* __restrict__ g4,
                        float4* __restrict__ out4)
{
    __shared__ __align__(16) float4 stage[3072];  // 8 warps * 4 rows * 96 = 48KB

    const int tid = threadIdx.x;
    const int t   = tid & 31;                     // lane == z-group (4 points)
    const int wid = tid >> 5;
    const int w4  = blockIdx.x * 8 + wid;         // quad id

    const int yp = w4 & 63;
    const int xp = (w4 >> 6) & 63;
    const int b  = w4 >> 12;
    const int y0 = yp << 1;
    const int x0 = xp << 1;

    float4* s = &stage[wid * 384];                // 4 rows: [x0,y0][x0,y0+1][x1,y0][x1,y0+1]

    // clamped neighbor indices (garbage rows only feed outputs that get zeroed)
    const int xm1 = (x0 == 0) ? 0 : (x0 - 1);
    const int ym1 = (y0 == 0) ? 0 : (y0 - 1);

    // 3x3 input-row neighborhood, all loads issued up front (MLP=9)
    const int gb = (b * S * S) * 32 + t;          // + (X*S + Y)*32
    const float4 R00 = __ldg(g4 + gb + (xm1      * S + ym1   ) * 32);
    const float4 R01 = __ldg(g4 + gb + (xm1      * S + y0    ) * 32);
    const float4 R02 = __ldg(g4 + gb + (xm1      * S + y0 + 1) * 32);
    const float4 R10 = __ldg(g4 + gb + (x0       * S + ym1   ) * 32);
    const float4 R11 = __ldg(g4 + gb + (x0       * S + y0    ) * 32);
    const float4 R12 = __ldg(g4 + gb + (x0       * S + y0 + 1) * 32);
    const float4 R20 = __ldg(g4 + gb + ((x0 + 1) * S + ym1   ) * 32);
    const float4 R21 = __ldg(g4 + gb + ((x0 + 1) * S + y0    ) * 32);
    const float4 R22 = __ldg(g4 + gb + ((x0 + 1) * S + y0 + 1) * 32);

    const float a00 = __shfl_up_sync(0xffffffffu, R00.w, 1);
    const float a01 = __shfl_up_sync(0xffffffffu, R01.w, 1);
    const float a02 = __shfl_up_sync(0xffffffffu, R02.w, 1);
    const float a10 = __shfl_up_sync(0xffffffffu, R10.w, 1);
    const float a11 = __shfl_up_sync(0xffffffffu, R11.w, 1);
    const float a12 = __shfl_up_sync(0xffffffffu, R12.w, 1);
    const float a20 = __shfl_up_sync(0xffffffffu, R20.w, 1);
    const float a21 = __shfl_up_sync(0xffffffffu, R21.w, 1);
    const float a22 = __shfl_up_sync(0xffffffffu, R22.w, 1);

    const float zf0 = (float)(t * 4);

    // rows at output x = x0 (zero if x0 == 0)
    if (x0 == 0) {
        zero_row(s, t);
        zero_row(s + 96, t);
    } else {
        if (y0 == 0) {
            zero_row(s, t);
        } else {
            compute_row(R00, R01, R10, R11, a00, a01, a10, a11,
                        (float)x0, (float)y0, zf0, t, s);
        }
        compute_row(R01, R02, R11, R12, a01, a02, a11, a12,
                    (float)x0, (float)(y0 + 1), zf0, t, s + 96);
    }

    // rows at output x = x0 + 1 (never 0)
    if (y0 == 0) {
        zero_row(s + 192, t);
    } else {
        compute_row(R10, R11, R20, R21, a10, a11, a20, a21,
                    (float)(x0 + 1), (float)y0, zf0, t, s + 192);
    }
    compute_row(R11, R12, R21, R22, a11, a12, a21, a22,
                (float)(x0 + 1), (float)(y0 + 1), zf0, t, s + 288);

    // per-warp drain: two 3KB bulk copies (the two x-rows are 128 output
    // rows apart in gmem), tagged evict_first.
    __syncwarp();
    if (t == 0) {
        float4* dst0 = out4 + ((size_t)(b * S + x0) * S + y0) * 96;
        float4* dst1 = dst0 + (size_t)S * 96;     // x0 + 1
        unsigned int sa;
        asm("{ .reg .u64 a; cvta.to.shared.u64 a, %1; cvt.u32.u64 %0, a; }"
            : "=r"(sa) : "l"(s));
        unsigned long long pol;
        asm("createpolicy.fractional.L2::evict_first.b64 %0, 1.0;" : "=l"(pol));
        asm volatile("fence.proxy.async.shared::cta;" ::: "memory");
        asm volatile(
            "cp.async.bulk.global.shared::cta.bulk_group.L2::cache_hint "
            "[%0], [%1], %2, %3;"
            :: "l"(dst0), "r"(sa), "r"(3072), "l"(pol) : "memory");
        asm volatile(
            "cp.async.bulk.global.shared::cta.bulk_group.L2::cache_hint "
            "[%0], [%1], %2, %3;"
            :: "l"(dst1), "r"(sa + 3072), "r"(3072), "l"(pol) : "memory");
        asm volatile("cp.async.bulk.commit_group;" ::: "memory");
        asm volatile("cp.async.bulk.wait_group 0;" ::: "memory");
    }
}

extern "C" void kernel_launch(void* const* d_in, const int* in_sizes, int n_in,
                              void* d_out, int out_size)
{
    const float4* g4 = (const float4*)d_in[0];
    float4* o4 = (float4*)d_out;

    const int total = in_sizes[0];          // B * 128^3
    const int nb = total >> 21;             // B
    const int nquads = nb * (S / 2) * (S / 2);   // one warp per 2x2 row tile
    const int blocks = nquads / 8;          // 8 quads per 256-thread block

    gridding_reverse_kernel<<<blocks, 256>>>(g4, o4);
}

// round 17
// speedup vs baseline: 1.3297x; 1.0303x over previous
#include <cuda_runtime.h>
#include <cstdint>

// GriddingReverse: grid [B,128,128,128] fp32 -> ptcloud [B, 128^3, 3] fp32.
//
// Round-17: R16 (2x2 heavy-warp tile, evict_first drains) won -> 23.9us.
// Remove the two remaining latency exposures without touching the structure:
//   1. overlap: issue the x0-pair drain BEFORE computing the x1 rows
//      (TMA copy runs concurrently with second-half compute); one wait at end
//   2. 128-thread blocks: smaller CTA-exit coupling on the drain wait,
//      8 CTAs/SM (24KB smem, 64 regs -> exactly full RF), occ 41->50%
// Unchanged: 9 LDG.128 / 4 output rows (MLP=9), shfl z-neighbor, s8 rewrite,
// folded epilogue, per-warp 3KB bulk drains with evict_first policy.

#define S 128
#define EPSF 1e-6f

__device__ __forceinline__ void zero_row(float4* s, int t)
{
    const float4 z4 = make_float4(0.f, 0.f, 0.f, 0.f);
    s[t * 3 + 0] = z4;
    s[t * 3 + 1] = z4;
    s[t * 3 + 2] = z4;
}

// Compute one output row from its 4 corner input rows.
// B00=(x-1,y-1) B01=(x-1,y) B10=(x,y-1) B11=(x,y); aXX = lane t-1's .w of BXX.
__device__ __forceinline__ void compute_row(
    float4 B00, float4 B01, float4 B10, float4 B11,
    float a00, float a01, float a10, float a11,
    float xf, float yf, float zf0, int t, float4* s)
{
    const float hi00[4] = {B00.x, B00.y, B00.z, B00.w};
    const float hi01[4] = {B01.x, B01.y, B01.z, B01.w};
    const float hi10[4] = {B10.x, B10.y, B10.z, B10.w};
    const float hi11[4] = {B11.x, B11.y, B11.z, B11.w};
    const float lo00[4] = {a00, B00.x, B00.y, B00.z};
    const float lo01[4] = {a01, B01.x, B01.y, B01.z};
    const float lo10[4] = {a10, B10.x, B10.y, B10.z};
    const float lo11[4] = {a11, B11.x, B11.y, B11.z};

    float res[12];

#pragma unroll
    for (int j = 0; j < 4; ++j) {
        const float p00 = lo00[j] + hi00[j];
        const float p01 = lo01[j] + hi01[j];
        const float p10 = lo10[j] + hi10[j];
        const float p11 = lo11[j] + hi11[j];

        const float x_lo = p00 + p01;                     // dx = 0 corners
        const float x_hi = p10 + p11;                     // dx = 1 corners
        const float s8   = x_lo + x_hi;                   // all 8 corners
        const float y_lo = p00 + p10;                     // dy = 0
        const float z_lo = (lo00[j] + lo01[j]) + (lo10[j] + lo11[j]);

        // (num/wsum - 64) * (1/64) == fma(num, (1/64)/wsum, -1)   [64*(1/64)==1]
        const float inv_s = __fdividef(0.015625f, s8 + EPSF);
        const float zf = zf0 + (float)j;

        // hi*c + lo*(c-1) == s8*c - lo
        float px = fmaf(fmaf(s8, xf, -x_lo), inv_s, -1.0f);
        float py = fmaf(fmaf(s8, yf, -y_lo), inv_s, -1.0f);
        float pz = fmaf(fmaf(s8, zf, -z_lo), inv_s, -1.0f);

        if (t == 0 && j == 0) { px = 0.f; py = 0.f; pz = 0.f; }  // z==0

        res[j * 3 + 0] = px;
        res[j * 3 + 1] = py;
        res[j * 3 + 2] = pz;
    }

    s[t * 3 + 0] = make_float4(res[0], res[1],  res[2],  res[3]);
    s[t * 3 + 1] = make_float4(res[4], res[5],  res[6],  res[7]);
    s[t * 3 + 2] = make_float4(res[8], res[9],  res[10], res[11]);
}

__device__ __forceinline__ void drain_3k(float4* dst, unsigned int sa,
                                         unsigned long long pol)
{
    asm volatile(
        "cp.async.bulk.global.shared::cta.bulk_group.L2::cache_hint "
        "[%0], [%1], %2, %3;"
        :: "l"(dst), "r"(sa), "r"(3072), "l"(pol) : "memory");
}

__global__ void __launch_bounds__(128, 8)
gridding_reverse_kernel(const float4* __restrict__ g4,
                        float4* __restrict__ out4)
{
    __shared__ __align__(16) float4 stage[1536];  // 4 warps * 4 rows * 96 = 24KB

    const int tid = threadIdx.x;
    const int t   = tid & 31;                     // lane == z-group (4 points)
    const int wid = tid >> 5;
    const int w4  = blockIdx.x * 4 + wid;         // quad id

    const int yp = w4 & 63;
    const int xp = (w4 >> 6) & 63;
    const int b  = w4 >> 12;
    const int y0 = yp << 1;
    const int x0 = xp << 1;

    float4* s = &stage[wid * 384];    // 4 rows: [x0,y0][x0,y0+1][x1,y0][x1,y0+1]

    // clamped neighbor indices (garbage rows only feed outputs that get zeroed)
    const int xm1 = (x0 == 0) ? 0 : (x0 - 1);
    const int ym1 = (y0 == 0) ? 0 : (y0 - 1);

    // 3x3 input-row neighborhood, all loads issued up front (MLP=9)
    const int gb = (b * S * S) * 32 + t;          // + (X*S + Y)*32
    const float4 R00 = __ldg(g4 + gb + (xm1      * S + ym1   ) * 32);
    const float4 R01 = __ldg(g4 + gb + (xm1      * S + y0    ) * 32);
    const float4 R02 = __ldg(g4 + gb + (xm1      * S + y0 + 1) * 32);
    const float4 R10 = __ldg(g4 + gb + (x0       * S + ym1   ) * 32);
    const float4 R11 = __ldg(g4 + gb + (x0       * S + y0    ) * 32);
    const float4 R12 = __ldg(g4 + gb + (x0       * S + y0 + 1) * 32);
    const float4 R20 = __ldg(g4 + gb + ((x0 + 1) * S + ym1   ) * 32);
    const float4 R21 = __ldg(g4 + gb + ((x0 + 1) * S + y0    ) * 32);
    const float4 R22 = __ldg(g4 + gb + ((x0 + 1) * S + y0 + 1) * 32);

    const float a00 = __shfl_up_sync(0xffffffffu, R00.w, 1);
    const float a01 = __shfl_up_sync(0xffffffffu, R01.w, 1);
    const float a02 = __shfl_up_sync(0xffffffffu, R02.w, 1);
    const float a10 = __shfl_up_sync(0xffffffffu, R10.w, 1);
    const float a11 = __shfl_up_sync(0xffffffffu, R11.w, 1);
    const float a12 = __shfl_up_sync(0xffffffffu, R12.w, 1);
    const float a20 = __shfl_up_sync(0xffffffffu, R20.w, 1);
    const float a21 = __shfl_up_sync(0xffffffffu, R21.w, 1);
    const float a22 = __shfl_up_sync(0xffffffffu, R22.w, 1);

    const float zf0 = (float)(t * 4);

    unsigned int sa;
    asm("{ .reg .u64 a; cvta.to.shared.u64 a, %1; cvt.u32.u64 %0, a; }"
        : "=r"(sa) : "l"(s));
    unsigned long long pol;
    asm("createpolicy.fractional.L2::evict_first.b64 %0, 1.0;" : "=l"(pol));
    float4* dst0 = out4 + ((size_t)(b * S + x0) * S + y0) * 96;

    // ── rows at output x = x0 (zero if x0 == 0), then drain immediately ──
    if (x0 == 0) {
        zero_row(s, t);
        zero_row(s + 96, t);
    } else {
        if (y0 == 0) {
            zero_row(s, t);
        } else {
            compute_row(R00, R01, R10, R11, a00, a01, a10, a11,
                        (float)x0, (float)y0, zf0, t, s);
        }
        compute_row(R01, R02, R11, R12, a01, a02, a11, a12,
                    (float)x0, (float)(y0 + 1), zf0, t, s + 96);
    }
    __syncwarp();
    if (t == 0) {
        asm volatile("fence.proxy.async.shared::cta;" ::: "memory");
        drain_3k(dst0, sa, pol);                  // overlaps with x1 compute
        asm volatile("cp.async.bulk.commit_group;" ::: "memory");
    }

    // ── rows at output x = x0 + 1 (never 0) ──
    if (y0 == 0) {
        zero_row(s + 192, t);
    } else {
        compute_row(R10, R11, R20, R21, a10, a11, a20, a21,
                    (float)(x0 + 1), (float)y0, zf0, t, s + 192);
    }
    compute_row(R11, R12, R21, R22, a11, a12, a21, a22,
                (float)(x0 + 1), (float)(y0 + 1), zf0, t, s + 288);

    __syncwarp();
    if (t == 0) {
        asm volatile("fence.proxy.async.shared::cta;" ::: "memory");
        drain_3k(dst0 + (size_t)S * 96, sa + 3072, pol);
        asm volatile("cp.async.bulk.commit_group;" ::: "memory");
        asm volatile("cp.async.bulk.wait_group 0;" ::: "memory");
    }
}

extern "C" void kernel_launch(void* const* d_in, const int* in_sizes, int n_in,
                              void* d_out, int out_size)
{
    const float4* g4 = (const float4*)d_in[0];
    float4* o4 = (float4*)d_out;

    const int total = in_sizes[0];          // B * 128^3
    const int nb = total >> 21;             // B
    const int nquads = nb * (S / 2) * (S / 2);   // one warp per 2x2 row tile
    const int blocks = nquads / 4;          // 4 quads per 128-thread block

    gridding_reverse_kernel<<<blocks, 128>>>(g4, o4);
}